// round 7
// baseline (speedup 1.0000x reference)
#include <cuda_runtime.h>
#include <cuda_bf16.h>

// Problem: B=512, S=512, I=64, C=4, H=100, O=7
// out = [output (512*7)] ++ [hidden_states (512*512*100)]
//
// Single fused scan kernel: the x-projection GEMM (Wf_x.xc, Wh_x.xc) is
// computed on the fly each step inside the recurrence kernel (it was
// latency-bound with idle issue slots), eliminating the separate pre-GEMM
// kernel and its 400MB scratch traffic entirely.

#define ULL unsigned long long

// ---------------- helpers ---------------------------------------------------
__device__ __forceinline__ ULL fma2(ULL a, ULL b, ULL c) {
    ULL d;
    asm("fma.rn.f32x2 %0, %1, %2, %3;" : "=l"(d) : "l"(a), "l"(b), "l"(c));
    return d;
}
__device__ __forceinline__ float hsum2(ULL a) {
    float lo, hi;
    asm("mov.b64 {%0,%1}, %2;" : "=f"(lo), "=f"(hi) : "l"(a));
    return lo + hi;
}
__device__ __forceinline__ float sigmoidf_(float v) {
    return __fdividef(1.f, 1.f + __expf(-v));
}
__device__ __forceinline__ float tanhf_(float v) {
    return 1.f - __fdividef(2.f, __expf(2.f * v) + 1.f);
}

// ---------------- fused scan -------------------------------------------------
// 128 blocks x 4 batch rows. 416 threads = 13 full warps.
//   j  = tid >> 2   (output unit, 0..103; 100..103 are dummies writing zeros)
//   kc = tid & 3    (k-chunk; also the batch row this thread owns in act phase)
// h-matvec chunk: k in [28kc, 28kc+28)  (kc=3: 16 real + 12 zero-pad)
// x-part  chunk: k in [16kc, 16kc+16)
// Partials for one j live in a lane quad -> reduced with 2x shfl.bfly.
// Only 2 __syncthreads per step.
__global__ void __launch_bounds__(416, 1)
scan_fused(const float* __restrict__ x, const float* __restrict__ ctx,
           const float* __restrict__ Wf_w, const float* __restrict__ Wf_b,
           const float* __restrict__ Wh_w, const float* __restrict__ Wh_b,
           float* __restrict__ hidden)
{
    const int tid = threadIdx.x;
    const int j  = tid >> 2;
    const int kc = tid & 3;
    const bool valid = (j < 100);
    const int jw = valid ? j : 99;          // clamped row for weight loads
    const int rbase = blockIdx.x * 4;

    __shared__ __align__(16) float sh_h[4][112];
    __shared__ __align__(16) float sh_fh[4][112];
    __shared__ __align__(16) float xs[2][4][64];   // double-buffered x tiles

    const int kb = 28 * kc;                 // h-chunk base
    const int xk = 16 * kc;                 // x-chunk base

    // ---- register-resident weights -----------------------------------------
    ULL wfh[14], whh[14], wfx[8], whx[8];
    {
        const int hp = (kc == 3) ? 8 : 14;  // real h-pairs in this chunk
        const ULL* pfh = (const ULL*)(Wf_w + jw * 168 + 68 + kb);
        const ULL* phh = (const ULL*)(Wh_w + jw * 168 + 68 + kb);
        #pragma unroll
        for (int t = 0; t < 14; t++) {
            wfh[t] = (t < hp) ? pfh[t] : 0ull;
            whh[t] = (t < hp) ? phh[t] : 0ull;
        }
        const ULL* pfx = (const ULL*)(Wf_w + jw * 168 + xk);
        const ULL* phx = (const ULL*)(Wh_w + jw * 168 + xk);
        #pragma unroll
        for (int t = 0; t < 8; t++) { wfx[t] = pfx[t]; whx[t] = phx[t]; }
    }
    // context-folded biases
    float cb_f = Wf_b[jw], cb_h = Wh_b[jw];
    #pragma unroll
    for (int cc = 0; cc < 4; cc++) {
        float cv = ctx[cc];
        cb_f += cv * Wf_w[jw * 168 + 64 + cc];
        cb_h += cv * Wh_w[jw * 168 + 64 + cc];
    }

    // ---- init shared (h0 = 0, zero padding must stay zero) -----------------
    for (int idx = tid; idx < 4 * 112; idx += 416) {
        (&sh_h[0][0])[idx]  = 0.f;
        (&sh_fh[0][0])[idx] = 0.f;
    }
    // prefetch x for s = 0
    if (tid < 256) {
        int r = tid >> 6, i = tid & 63;
        xs[0][r][i] = x[((size_t)(rbase + r) * 512) * 64 + i];
    }
    __syncthreads();

    #pragma unroll 1
    for (int s = 0; s < 512; s++) {
        const int buf = s & 1;

        // prefetch x for s+1 into the other buffer (safe: previous readers of
        // that buffer finished before last step's closing barrier)
        if (tid < 256) {
            int r = tid >> 6, i = tid & 63;
            int sp = (s < 511) ? s + 1 : 511;
            xs[buf ^ 1][r][i] = x[((size_t)(rbase + r) * 512 + sp) * 64 + i];
        }

        // ---- MV1: Wf_h . h + Wf_x . x  (own chunks, 4 rows) ----------------
        ULL a0 = 0ull, a1 = 0ull, a2 = 0ull, a3 = 0ull;
        #pragma unroll
        for (int t = 0; t < 7; t++) {
            ulonglong2 h0 = *(const ulonglong2*)&sh_h[0][kb + 4 * t];
            ulonglong2 h1 = *(const ulonglong2*)&sh_h[1][kb + 4 * t];
            ulonglong2 h2 = *(const ulonglong2*)&sh_h[2][kb + 4 * t];
            ulonglong2 h3 = *(const ulonglong2*)&sh_h[3][kb + 4 * t];
            a0 = fma2(wfh[2 * t], h0.x, a0); a0 = fma2(wfh[2 * t + 1], h0.y, a0);
            a1 = fma2(wfh[2 * t], h1.x, a1); a1 = fma2(wfh[2 * t + 1], h1.y, a1);
            a2 = fma2(wfh[2 * t], h2.x, a2); a2 = fma2(wfh[2 * t + 1], h2.y, a2);
            a3 = fma2(wfh[2 * t], h3.x, a3); a3 = fma2(wfh[2 * t + 1], h3.y, a3);
        }
        #pragma unroll
        for (int t = 0; t < 4; t++) {
            ulonglong2 x0 = *(const ulonglong2*)&xs[buf][0][xk + 4 * t];
            ulonglong2 x1 = *(const ulonglong2*)&xs[buf][1][xk + 4 * t];
            ulonglong2 x2 = *(const ulonglong2*)&xs[buf][2][xk + 4 * t];
            ulonglong2 x3 = *(const ulonglong2*)&xs[buf][3][xk + 4 * t];
            a0 = fma2(wfx[2 * t], x0.x, a0); a0 = fma2(wfx[2 * t + 1], x0.y, a0);
            a1 = fma2(wfx[2 * t], x1.x, a1); a1 = fma2(wfx[2 * t + 1], x1.y, a1);
            a2 = fma2(wfx[2 * t], x2.x, a2); a2 = fma2(wfx[2 * t + 1], x2.y, a2);
            a3 = fma2(wfx[2 * t], x3.x, a3); a3 = fma2(wfx[2 * t + 1], x3.y, a3);
        }
        float f0 = hsum2(a0), f1 = hsum2(a1), f2 = hsum2(a2), f3 = hsum2(a3);
        f0 += __shfl_xor_sync(0xFFFFFFFFu, f0, 1);
        f1 += __shfl_xor_sync(0xFFFFFFFFu, f1, 1);
        f2 += __shfl_xor_sync(0xFFFFFFFFu, f2, 1);
        f3 += __shfl_xor_sync(0xFFFFFFFFu, f3, 1);
        f0 += __shfl_xor_sync(0xFFFFFFFFu, f0, 2);
        f1 += __shfl_xor_sync(0xFFFFFFFFu, f1, 2);
        f2 += __shfl_xor_sync(0xFFFFFFFFu, f2, 2);
        f3 += __shfl_xor_sync(0xFFFFFFFFu, f3, 2);

        // lane kc owns batch row kc
        float pre_f = (kc == 0 ? f0 : kc == 1 ? f1 : kc == 2 ? f2 : f3) + cb_f;
        float fg   = sigmoidf_(pre_f);
        float hold = sh_h[kc][j];
        sh_fh[kc][j] = valid ? fg * hold : 0.f;
        __syncthreads();  // (1) sh_fh visible

        // ---- MV2: Wh_h . (f*h) + Wh_x . x ----------------------------------
        a0 = a1 = a2 = a3 = 0ull;
        #pragma unroll
        for (int t = 0; t < 7; t++) {
            ulonglong2 h0 = *(const ulonglong2*)&sh_fh[0][kb + 4 * t];
            ulonglong2 h1 = *(const ulonglong2*)&sh_fh[1][kb + 4 * t];
            ulonglong2 h2 = *(const ulonglong2*)&sh_fh[2][kb + 4 * t];
            ulonglong2 h3 = *(const ulonglong2*)&sh_fh[3][kb + 4 * t];
            a0 = fma2(whh[2 * t], h0.x, a0); a0 = fma2(whh[2 * t + 1], h0.y, a0);
            a1 = fma2(whh[2 * t], h1.x, a1); a1 = fma2(whh[2 * t + 1], h1.y, a1);
            a2 = fma2(whh[2 * t], h2.x, a2); a2 = fma2(whh[2 * t + 1], h2.y, a2);
            a3 = fma2(whh[2 * t], h3.x, a3); a3 = fma2(whh[2 * t + 1], h3.y, a3);
        }
        #pragma unroll
        for (int t = 0; t < 4; t++) {
            ulonglong2 x0 = *(const ulonglong2*)&xs[buf][0][xk + 4 * t];
            ulonglong2 x1 = *(const ulonglong2*)&xs[buf][1][xk + 4 * t];
            ulonglong2 x2 = *(const ulonglong2*)&xs[buf][2][xk + 4 * t];
            ulonglong2 x3 = *(const ulonglong2*)&xs[buf][3][xk + 4 * t];
            a0 = fma2(whx[2 * t], x0.x, a0); a0 = fma2(whx[2 * t + 1], x0.y, a0);
            a1 = fma2(whx[2 * t], x1.x, a1); a1 = fma2(whx[2 * t + 1], x1.y, a1);
            a2 = fma2(whx[2 * t], x2.x, a2); a2 = fma2(whx[2 * t + 1], x2.y, a2);
            a3 = fma2(whx[2 * t], x3.x, a3); a3 = fma2(whx[2 * t + 1], x3.y, a3);
        }
        f0 = hsum2(a0); f1 = hsum2(a1); f2 = hsum2(a2); f3 = hsum2(a3);
        f0 += __shfl_xor_sync(0xFFFFFFFFu, f0, 1);
        f1 += __shfl_xor_sync(0xFFFFFFFFu, f1, 1);
        f2 += __shfl_xor_sync(0xFFFFFFFFu, f2, 1);
        f3 += __shfl_xor_sync(0xFFFFFFFFu, f3, 1);
        f0 += __shfl_xor_sync(0xFFFFFFFFu, f0, 2);
        f1 += __shfl_xor_sync(0xFFFFFFFFu, f1, 2);
        f2 += __shfl_xor_sync(0xFFFFFFFFu, f2, 2);
        f3 += __shfl_xor_sync(0xFFFFFFFFu, f3, 2);

        float pre_h = (kc == 0 ? f0 : kc == 1 ? f1 : kc == 2 ? f2 : f3) + cb_h;
        float ht = tanhf_(pre_h);
        float hn = hold + fg * (ht - hold);
        sh_h[kc][j] = valid ? hn : 0.f;
        if (valid)
            hidden[((size_t)(rbase + kc) * 512 + s) * 100 + j] = hn;
        __syncthreads();  // (2) sh_h visible for next step; orders x prefetch
    }
}

// ---------------- output head ------------------------------------------------
__global__ void head_kernel(const float* __restrict__ hidden,
                            const float* __restrict__ ro_w,
                            const float* __restrict__ ro_b,
                            float* __restrict__ out)
{
    int t = blockIdx.x * blockDim.x + threadIdx.x;
    if (t >= 512 * 7) return;
    int b = t / 7, o = t % 7;
    const float* h = hidden + ((size_t)b * 512 + 511) * 100;
    const float* w = ro_w + o * 100;
    float acc = ro_b[o];
    #pragma unroll 4
    for (int k = 0; k < 100; k++) acc += h[k] * w[k];
    out[t] = acc;
}

// ---------------- launch -----------------------------------------------------
extern "C" void kernel_launch(void* const* d_in, const int* in_sizes, int n_in,
                              void* d_out, int out_size)
{
    (void)in_sizes; (void)n_in; (void)out_size;
    const float* x     = (const float*)d_in[0];
    const float* ctx   = (const float*)d_in[1];
    const float* Wf_w  = (const float*)d_in[2];
    const float* Wf_b  = (const float*)d_in[3];
    const float* Wh_w  = (const float*)d_in[4];
    const float* Wh_b  = (const float*)d_in[5];
    const float* ro_w  = (const float*)d_in[6];
    const float* ro_b  = (const float*)d_in[7];

    float* out    = (float*)d_out;
    float* hidden = out + 512 * 7;

    scan_fused<<<128, 416>>>(x, ctx, Wf_w, Wf_b, Wh_w, Wh_b, hidden);
    head_kernel<<<14, 256>>>(hidden, ro_w, ro_b, out);
}

// round 8
// speedup vs baseline: 1.4280x; 1.4280x over previous
#include <cuda_runtime.h>
#include <cuda_bf16.h>

// Problem: B=512, S=512, I=64, C=4, H=100, O=7
// out = [output (512*7)] ++ [hidden_states (512*512*100)]

#define ULL unsigned long long

// ---------------- scratch (device globals; no runtime allocation) -----------
__device__ float g_xf[512 * 512 * 100];
__device__ float g_xh[512 * 512 * 100];

// ---------------- helpers ---------------------------------------------------
__device__ __forceinline__ ULL fma2(ULL a, ULL b, ULL c) {
    ULL d;
    asm("fma.rn.f32x2 %0, %1, %2, %3;" : "=l"(d) : "l"(a), "l"(b), "l"(c));
    return d;
}
__device__ __forceinline__ float hsum2(ULL a) {
    float lo, hi;
    asm("mov.b64 {%0,%1}, %2;" : "=f"(lo), "=f"(hi) : "l"(a));
    return lo + hi;
}
__device__ __forceinline__ void unpack2(ULL a, float& lo, float& hi) {
    asm("mov.b64 {%0,%1}, %2;" : "=f"(lo), "=f"(hi) : "l"(a));
}
__device__ __forceinline__ ULL dup2(float v) {
    ULL d;
    asm("mov.b64 %0, {%1,%1};" : "=l"(d) : "f"(v));
    return d;
}
__device__ __forceinline__ float sigmoidf_(float v) {
    return __fdividef(1.f, 1.f + __expf(-v));
}
__device__ __forceinline__ float tanhf_(float v) {
    return 1.f - __fdividef(2.f, __expf(2.f * v) + 1.f);
}

// ---------------- K1: pre-GEMM, register-blocked -----------------------------
// 2048 blocks x 256 threads. Tile: 128 positions x 64 rows/pass (4 passes over
// 200 stacked rows: 0..99 = f-gate, 100..199 = h-gate).
// Thread (pg = tid&31, jg = tid>>5): frag = 8 rows (4 j-pair ULLs) x 4 pos.
// x transposed in shared [k][pos] (conflict-free pos-consecutive reads);
// w transposed in shared [k][row] (full-warp broadcast reads).
// Shared bytes per MAC = 0.5 (was 4.0) -> crossbar no longer binds.
#define PRE_XS   (64 * 128)          // floats
#define PRE_WS   (64 * 68)           // floats (pitch 68 spreads STS banks)
#define PRE_CB   256
#define PRE_SMEM ((PRE_XS + PRE_WS + PRE_CB) * 4)

__global__ void __launch_bounds__(256, 2)
pre_kernel(const float* __restrict__ x, const float* __restrict__ ctx,
           const float* __restrict__ Wf_w, const float* __restrict__ Wf_b,
           const float* __restrict__ Wh_w, const float* __restrict__ Wh_b)
{
    extern __shared__ float sm[];
    float* xs = sm;                    // [64][128]
    float* ws = sm + PRE_XS;           // [64][68]
    float* cb = sm + PRE_XS + PRE_WS;  // [256] ctx-folded bias per row

    const int tid = threadIdx.x;
    const int pg = tid & 31;
    const int jg = tid >> 5;
    const size_t pbase = (size_t)blockIdx.x * 128;

    // ctx-folded bias for all 200 rows (pad rows -> 0)
    {
        int r = tid;
        float v = 0.f;
        if (r < 200) {
            const float* W = (r < 100) ? (Wf_w + r * 168) : (Wh_w + (r - 100) * 168);
            v = (r < 100) ? Wf_b[r] : Wh_b[r - 100];
            #pragma unroll
            for (int c = 0; c < 4; c++) v += ctx[c] * W[64 + c];
        }
        cb[r] = v;
    }

    // load x tile transposed: x[pbase+p][k] -> xs[k][p]
    for (int idx = tid; idx < 2048; idx += 256) {
        int p = idx >> 4, k4 = (idx & 15) << 2;
        float4 v = *(const float4*)(x + (pbase + p) * 64 + k4);
        xs[(k4 + 0) * 128 + p] = v.x;
        xs[(k4 + 1) * 128 + p] = v.y;
        xs[(k4 + 2) * 128 + p] = v.z;
        xs[(k4 + 3) * 128 + p] = v.w;
    }
    __syncthreads();

    #pragma unroll 1
    for (int pass = 0; pass < 4; pass++) {
        // load this pass's 64 rows of weights transposed: W[row][k] -> ws[k][row]
        for (int idx = tid; idx < 1024; idx += 256) {
            int row = idx >> 4, k4 = (idx & 15) << 2;
            int rg = pass * 64 + row;
            int rc = (rg < 200) ? rg : 199;   // clamp (values unused if invalid)
            const float* W = (rc < 100) ? (Wf_w + rc * 168) : (Wh_w + (rc - 100) * 168);
            float4 v = *(const float4*)(W + k4);
            ws[(k4 + 0) * 68 + row] = v.x;
            ws[(k4 + 1) * 68 + row] = v.y;
            ws[(k4 + 2) * 68 + row] = v.z;
            ws[(k4 + 3) * 68 + row] = v.w;
        }
        __syncthreads();

        ULL acc[4][4];  // [j-pair][pos]
        #pragma unroll
        for (int a = 0; a < 4; a++)
            #pragma unroll
            for (int b = 0; b < 4; b++) acc[a][b] = 0ull;

        #pragma unroll 8
        for (int k = 0; k < 64; k++) {
            float4 xv = *(const float4*)(xs + k * 128 + pg * 4);
            ulonglong2 wa = *(const ulonglong2*)(ws + k * 68 + jg * 8);
            ulonglong2 wb = *(const ulonglong2*)(ws + k * 68 + jg * 8 + 4);
            ULL x0 = dup2(xv.x), x1 = dup2(xv.y), x2 = dup2(xv.z), x3 = dup2(xv.w);
            acc[0][0] = fma2(wa.x, x0, acc[0][0]);
            acc[0][1] = fma2(wa.x, x1, acc[0][1]);
            acc[0][2] = fma2(wa.x, x2, acc[0][2]);
            acc[0][3] = fma2(wa.x, x3, acc[0][3]);
            acc[1][0] = fma2(wa.y, x0, acc[1][0]);
            acc[1][1] = fma2(wa.y, x1, acc[1][1]);
            acc[1][2] = fma2(wa.y, x2, acc[1][2]);
            acc[1][3] = fma2(wa.y, x3, acc[1][3]);
            acc[2][0] = fma2(wb.x, x0, acc[2][0]);
            acc[2][1] = fma2(wb.x, x1, acc[2][1]);
            acc[2][2] = fma2(wb.x, x2, acc[2][2]);
            acc[2][3] = fma2(wb.x, x3, acc[2][3]);
            acc[3][0] = fma2(wb.y, x0, acc[3][0]);
            acc[3][1] = fma2(wb.y, x1, acc[3][1]);
            acc[3][2] = fma2(wb.y, x2, acc[3][2]);
            acc[3][3] = fma2(wb.y, x3, acc[3][3]);
        }

        // epilogue: rows rb..rb+7, positions pbase + 4pg + {0..3}
        const int rb = pass * 64 + jg * 8;
        float c0 = cb[rb + 0], c1 = cb[rb + 1], c2 = cb[rb + 2], c3 = cb[rb + 3];
        float c4 = cb[rb + 4], c5 = cb[rb + 5], c6 = cb[rb + 6], c7 = cb[rb + 7];
        #pragma unroll
        for (int i = 0; i < 4; i++) {
            size_t pos = pbase + pg * 4 + i;
            float v0, v1, v2, v3, v4, v5, v6, v7;
            unpack2(acc[0][i], v0, v1);
            unpack2(acc[1][i], v2, v3);
            unpack2(acc[2][i], v4, v5);
            unpack2(acc[3][i], v6, v7);
            // group rb..rb+3 (never straddles the f/h boundary: all mult-of-4)
            if (rb < 200) {
                float* dst = (rb < 100) ? (g_xf + pos * 100 + rb)
                                        : (g_xh + pos * 100 + rb - 100);
                *(float4*)dst = make_float4(v0 + c0, v1 + c1, v2 + c2, v3 + c3);
            }
            int r4 = rb + 4;
            if (r4 < 200) {
                float* dst = (r4 < 100) ? (g_xf + pos * 100 + r4)
                                        : (g_xh + pos * 100 + r4 - 100);
                *(float4*)dst = make_float4(v4 + c4, v5 + c5, v6 + c6, v7 + c7);
            }
        }
        __syncthreads();  // ws reused next pass
    }
}

// ---------------- K2: sequential scan, quad-shfl reduction -------------------
// 128 blocks x 4 batch rows. 416 threads = 13 full warps.
//   j  = tid >> 2 (output unit, 0..103; 100..103 dummies keep padding zero)
//   kc = tid & 3  (k-chunk; also the batch row this thread owns in act phase)
// h-matvec chunk: k in [28kc, 28kc+28) (kc=3: 16 real + 12 zero-pad).
// Partials for one j live in a lane quad -> 2x shfl.bfly, no shared exchange.
// 2 __syncthreads per step. Only h-weights in regs (56 regs) -> no spill.
__global__ void __launch_bounds__(416, 1)
scan_kernel(const float* __restrict__ Wf_w, const float* __restrict__ Wh_w,
            float* __restrict__ hidden)
{
    const int tid = threadIdx.x;
    const int j  = tid >> 2;
    const int kc = tid & 3;
    const bool valid = (j < 100);
    const int jw = valid ? j : 99;
    const int rbase = blockIdx.x * 4;
    const int kb = 28 * kc;

    __shared__ __align__(16) float sh_h[4][112];
    __shared__ __align__(16) float sh_fh[4][112];

    // register-resident recurrence weights (k-pair packed), pad pairs = 0
    ULL wfh[14], whh[14];
    {
        const int hp = (kc == 3) ? 8 : 14;
        const ULL* pf = (const ULL*)(Wf_w + jw * 168 + 68 + kb);
        const ULL* ph = (const ULL*)(Wh_w + jw * 168 + 68 + kb);
        #pragma unroll
        for (int t = 0; t < 14; t++) {
            wfh[t] = (t < hp) ? pf[t] : 0ull;
            whh[t] = (t < hp) ? ph[t] : 0ull;
        }
    }

    for (int idx = tid; idx < 4 * 112; idx += 416) {
        (&sh_h[0][0])[idx]  = 0.f;
        (&sh_fh[0][0])[idx] = 0.f;
    }
    __syncthreads();

    // prefetched gate pre-activations: thread (j,kc) owns batch row kc
    const size_t xbase = (size_t)(rbase + kc) * 51200 + jw;
    float xf_cur = g_xf[xbase];
    float xh_cur = g_xh[xbase];

    #pragma unroll 1
    for (int s = 0; s < 512; s++) {
        // ---- MV1: Wf_h . h (own chunk, 4 rows) -----------------------------
        ULL a0 = 0ull, a1 = 0ull, a2 = 0ull, a3 = 0ull;
        #pragma unroll
        for (int t = 0; t < 7; t++) {
            ulonglong2 h0 = *(const ulonglong2*)&sh_h[0][kb + 4 * t];
            ulonglong2 h1 = *(const ulonglong2*)&sh_h[1][kb + 4 * t];
            ulonglong2 h2 = *(const ulonglong2*)&sh_h[2][kb + 4 * t];
            ulonglong2 h3 = *(const ulonglong2*)&sh_h[3][kb + 4 * t];
            a0 = fma2(wfh[2 * t], h0.x, a0); a0 = fma2(wfh[2 * t + 1], h0.y, a0);
            a1 = fma2(wfh[2 * t], h1.x, a1); a1 = fma2(wfh[2 * t + 1], h1.y, a1);
            a2 = fma2(wfh[2 * t], h2.x, a2); a2 = fma2(wfh[2 * t + 1], h2.y, a2);
            a3 = fma2(wfh[2 * t], h3.x, a3); a3 = fma2(wfh[2 * t + 1], h3.y, a3);
        }
        float f0 = hsum2(a0), f1 = hsum2(a1), f2 = hsum2(a2), f3 = hsum2(a3);
        f0 += __shfl_xor_sync(0xFFFFFFFFu, f0, 1);
        f1 += __shfl_xor_sync(0xFFFFFFFFu, f1, 1);
        f2 += __shfl_xor_sync(0xFFFFFFFFu, f2, 1);
        f3 += __shfl_xor_sync(0xFFFFFFFFu, f3, 1);
        f0 += __shfl_xor_sync(0xFFFFFFFFu, f0, 2);
        f1 += __shfl_xor_sync(0xFFFFFFFFu, f1, 2);
        f2 += __shfl_xor_sync(0xFFFFFFFFu, f2, 2);
        f3 += __shfl_xor_sync(0xFFFFFFFFu, f3, 2);

        float pre_f = (kc == 0 ? f0 : kc == 1 ? f1 : kc == 2 ? f2 : f3) + xf_cur;
        float fg   = sigmoidf_(pre_f);
        float hold = sh_h[kc][j];
        sh_fh[kc][j] = valid ? fg * hold : 0.f;

        // prefetch next step's pre-activations (overlaps barrier)
        int sp = (s < 511) ? s + 1 : 511;
        float xf_nxt = g_xf[xbase + (size_t)sp * 100];
        float xh_nxt = g_xh[xbase + (size_t)sp * 100];
        __syncthreads();  // (1) sh_fh visible

        // ---- MV2: Wh_h . (f*h) ---------------------------------------------
        a0 = a1 = a2 = a3 = 0ull;
        #pragma unroll
        for (int t = 0; t < 7; t++) {
            ulonglong2 h0 = *(const ulonglong2*)&sh_fh[0][kb + 4 * t];
            ulonglong2 h1 = *(const ulonglong2*)&sh_fh[1][kb + 4 * t];
            ulonglong2 h2 = *(const ulonglong2*)&sh_fh[2][kb + 4 * t];
            ulonglong2 h3 = *(const ulonglong2*)&sh_fh[3][kb + 4 * t];
            a0 = fma2(whh[2 * t], h0.x, a0); a0 = fma2(whh[2 * t + 1], h0.y, a0);
            a1 = fma2(whh[2 * t], h1.x, a1); a1 = fma2(whh[2 * t + 1], h1.y, a1);
            a2 = fma2(whh[2 * t], h2.x, a2); a2 = fma2(whh[2 * t + 1], h2.y, a2);
            a3 = fma2(whh[2 * t], h3.x, a3); a3 = fma2(whh[2 * t + 1], h3.y, a3);
        }
        f0 = hsum2(a0); f1 = hsum2(a1); f2 = hsum2(a2); f3 = hsum2(a3);
        f0 += __shfl_xor_sync(0xFFFFFFFFu, f0, 1);
        f1 += __shfl_xor_sync(0xFFFFFFFFu, f1, 1);
        f2 += __shfl_xor_sync(0xFFFFFFFFu, f2, 1);
        f3 += __shfl_xor_sync(0xFFFFFFFFu, f3, 1);
        f0 += __shfl_xor_sync(0xFFFFFFFFu, f0, 2);
        f1 += __shfl_xor_sync(0xFFFFFFFFu, f1, 2);
        f2 += __shfl_xor_sync(0xFFFFFFFFu, f2, 2);
        f3 += __shfl_xor_sync(0xFFFFFFFFu, f3, 2);

        float pre_h = (kc == 0 ? f0 : kc == 1 ? f1 : kc == 2 ? f2 : f3) + xh_cur;
        float ht = tanhf_(pre_h);
        float hn = hold + fg * (ht - hold);
        sh_h[kc][j] = valid ? hn : 0.f;
        if (valid)
            hidden[((size_t)(rbase + kc) * 512 + s) * 100 + j] = hn;
        xf_cur = xf_nxt;
        xh_cur = xh_nxt;
        __syncthreads();  // (2) sh_h visible for next step
    }
}

// ---------------- K3: output head (warp per output) --------------------------
__global__ void head_kernel(const float* __restrict__ hidden,
                            const float* __restrict__ ro_w,
                            const float* __restrict__ ro_b,
                            float* __restrict__ out)
{
    int warp = (blockIdx.x * blockDim.x + threadIdx.x) >> 5;
    int lane = threadIdx.x & 31;
    if (warp >= 512 * 7) return;
    int b = warp / 7, o = warp - b * 7;
    const float* h = hidden + ((size_t)b * 512 + 511) * 100;
    const float* w = ro_w + o * 100;
    float acc = 0.f;
    for (int k = lane; k < 100; k += 32) acc += h[k] * w[k];
    #pragma unroll
    for (int d = 16; d; d >>= 1) acc += __shfl_xor_sync(0xFFFFFFFFu, acc, d);
    if (lane == 0) out[b * 7 + o] = acc + ro_b[o];
}

// ---------------- launch -----------------------------------------------------
extern "C" void kernel_launch(void* const* d_in, const int* in_sizes, int n_in,
                              void* d_out, int out_size)
{
    (void)in_sizes; (void)n_in; (void)out_size;
    const float* x     = (const float*)d_in[0];
    const float* ctx   = (const float*)d_in[1];
    const float* Wf_w  = (const float*)d_in[2];
    const float* Wf_b  = (const float*)d_in[3];
    const float* Wh_w  = (const float*)d_in[4];
    const float* Wh_b  = (const float*)d_in[5];
    const float* ro_w  = (const float*)d_in[6];
    const float* ro_b  = (const float*)d_in[7];

    float* out    = (float*)d_out;
    float* hidden = out + 512 * 7;

    cudaFuncSetAttribute(pre_kernel,
                         cudaFuncAttributeMaxDynamicSharedMemorySize, PRE_SMEM);
    pre_kernel<<<2048, 256, PRE_SMEM>>>(x, ctx, Wf_w, Wf_b, Wh_w, Wh_b);
    scan_kernel<<<128, 416>>>(Wf_w, Wh_w, hidden);
    head_kernel<<<448, 256>>>(hidden, ro_w, ro_b, out);
}